// round 4
// baseline (speedup 1.0000x reference)
#include <cuda_runtime.h>

#define NG 21
#define NTRIP 69

typedef unsigned long long ull;

struct Meta {
    const float* f[6];
    const float* w[6];
    float*       out;
    int cg_off[NG][6];
    int col_base[NG][6];
    int trip_l1[NTRIP];
    int trip_l2[NTRIP];
    int trip_l[NTRIP];
    int trip_off[NTRIP];
};

__device__ float d_cg[4096];
__device__ float d_wt[565248];   // transposed weights, all l concatenated

__constant__ int c_NUMCOLS[6] = {1536, 2560, 3328, 3584, 3584, 3072};
__constant__ int c_FOFF[7]    = {0, 32, 128, 288, 512, 800, 1152};
__constant__ int c_OUTOFF[6]  = {0, 8192, 32768, 73728, 131072, 204800};
__constant__ int c_WTOFF[6]   = {0, 49152, 131072, 237568, 352256, 466944};

__constant__ double c_fact[17] = {
    1.0, 1.0, 2.0, 6.0, 24.0, 120.0, 720.0, 5040.0, 40320.0, 362880.0,
    3628800.0, 39916800.0, 479001600.0, 6227020800.0, 87178291200.0,
    1307674368000.0, 20922789888000.0
};

// ---- packed f32x2 helpers -------------------------------------------------
__device__ __forceinline__ ull pk2(float a, float b) {
    ull r; asm("mov.b64 %0, {%1,%2};" : "=l"(r) : "f"(a), "f"(b)); return r;
}
__device__ __forceinline__ ull ffma2(ull a, ull b, ull c) {
    ull d; asm("fma.rn.f32x2 %0, %1, %2, %3;" : "=l"(d) : "l"(a), "l"(b), "l"(c)); return d;
}
__device__ __forceinline__ float2 upk(ull a) {
    float2 r; asm("mov.b64 {%0,%1}, %2;" : "=f"(r.x), "=f"(r.y) : "l"(a)); return r;
}

// ---------------------------------------------------------------------------
// CG coefficient init (Racah formula). One CTA per (l1,l2,l) triple.
// ---------------------------------------------------------------------------
__device__ double cg_coeff_d(int l1, int l2, int l, int m1, int m2, int m) {
    double pref = sqrt((2.0 * l + 1.0) * c_fact[l + l1 - l2] * c_fact[l - l1 + l2] *
                       c_fact[l1 + l2 - l] / c_fact[l1 + l2 + l + 1]);
    pref *= sqrt(c_fact[l + m] * c_fact[l - m] * c_fact[l1 - m1] * c_fact[l1 + m1] *
                 c_fact[l2 - m2] * c_fact[l2 + m2]);
    int kmin = 0;
    if (l2 - l - m1 > kmin) kmin = l2 - l - m1;
    if (l1 + m2 - l > kmin) kmin = l1 + m2 - l;
    int kmax = l1 + l2 - l;
    if (l1 - m1 < kmax) kmax = l1 - m1;
    if (l2 + m2 < kmax) kmax = l2 + m2;
    double s = 0.0;
    for (int k = kmin; k <= kmax; k++) {
        double d = c_fact[k] * c_fact[l1 + l2 - l - k] * c_fact[l1 - m1 - k] *
                   c_fact[l2 + m2 - k] * c_fact[l - l2 + m1 + k] * c_fact[l - l1 - m2 + k];
        s += ((k & 1) ? -1.0 : 1.0) / d;
    }
    return pref * s;
}

__global__ void cg_init_kernel(Meta meta) {
    int tr = blockIdx.x;
    int l1 = meta.trip_l1[tr], l2 = meta.trip_l2[tr], l = meta.trip_l[tr];
    int off = meta.trip_off[tr];
    int n1 = 2 * l1 + 1, n2 = 2 * l2 + 1;
    int idx = threadIdx.x;
    if (idx >= n1 * n2) return;
    int m1i = idx / n2, m2i = idx % n2;
    int m1 = m1i - l1, m2 = m2i - l2, m = m1 + m2;
    float c = 0.0f;
    if (m >= -l && m <= l)
        c = (float)cg_coeff_d(l1, l2, l, m1, m2, m);
    d_cg[off + idx] = c;
}

// ---------------------------------------------------------------------------
// Weight transpose: w[l][t][c][2] -> wt[l][c/2][t][4]
// ---------------------------------------------------------------------------
__global__ void wt_kernel(Meta m) {
    int j = blockIdx.x * blockDim.x + threadIdx.x;
    if (j >= 565248) return;
    int l = 0;
#pragma unroll
    for (int ll = 1; ll < 6; ll++)
        if (j >= c_WTOFF[ll]) l = ll;
    int r = j - c_WTOFF[l];
    int q = r & 3;
    int pt = r >> 2;
    int t = pt & 15;
    int p = pt >> 4;
    int c = 2 * p + (q >> 1);
    int ri = q & 1;
    d_wt[j] = m.w[l][(t * c_NUMCOLS[l] + c) * 2 + ri];
}

// ---------------------------------------------------------------------------
// Main fused kernel
// ---------------------------------------------------------------------------
template <int L1, int L2, int LA, int LB>
__device__ __forceinline__ void process_range(
    int g, const Meta& meta, float* __restrict__ f_s, float* __restrict__ out_s,
    float* __restrict__ cg_s, int* __restrict__ lutA, int* __restrict__ lutB,
    float* __restrict__ frag_s, int tid)
{
    constexpr int N1 = 2 * L1 + 1;
    constexpr int N2 = 2 * L2 + 1;
    constexpr int STRIDE = N1 * N2;
    constexpr int NL = LB - LA + 1;
    constexpr int SK = (LB + 1) * (LB + 1) - LA * LA;
    constexpr int KP = ((LB + 1) * (LB + 2) - LA * (LA + 1)) / 2;  // Σ(l+1)
    constexpr int E2 = 16 * KP;   // <= 256 for all our subranges

    __syncthreads();  // prior phase done with cg/lut/frag

    {
        const float* src = d_cg + meta.cg_off[g][LA];
        for (int s = tid; s < NL * STRIDE; s += 256) cg_s[s] = src[s];
    }
    // build k-paired work list: entry = (t, pp) where pp indexes (l, k-pair)
    if (tid < E2) {
        int t = tid & 15, pp = tid >> 4;
        int l = LA;
#pragma unroll
        for (int ll = LA; ll < LB; ll++)
            if (pp >= ((ll + 1) * (ll + 2) - LA * (LA + 1)) / 2) l = ll + 1;
        int cumP = (l * (l + 1) - LA * (LA + 1)) / 2;
        int k0 = 2 * (pp - cumP);
        int kk0 = (l * l - LA * LA) + k0;
        int dual = (k0 < 2 * l) ? 1 : 0;
        int ooff = c_FOFF[l] + (t * (2 * l + 1) + k0) * 2;
        lutA[tid] = c_WTOFF[l] + (meta.col_base[g][l] >> 1) * 64 + t * 4;
        lutB[tid] = (kk0 << 16) | (dual << 15) | ooff;
    }
    __syncthreads();  // cg + lut ready

    // ---- stage 1: CG fragments, thread = (i,j) channel pair = column ----
    {
        int i = tid >> 4, j = tid & 15;
        ull acc[SK];
#pragma unroll
        for (int q = 0; q < SK; q++) acc[q] = 0ull;
        const float* f1 = f_s + c_FOFF[L1] + i * N1 * 2;
        const float* f2 = f_s + c_FOFF[L2] + j * N2 * 2;
#pragma unroll
        for (int m1 = 0; m1 < N1; m1++) {
            float ar = f1[2 * m1], ai = f1[2 * m1 + 1];
#pragma unroll
            for (int m2 = 0; m2 < N2; m2++) {
                float br = f2[2 * m2], bi = f2[2 * m2 + 1];
                float pr = ar * br - ai * bi;
                float pi = ar * bi + ai * br;
                ull pp2 = pk2(pr, pi);
                int m = m1 + m2 - L1 - L2;
#pragma unroll
                for (int l = LA; l <= LB; l++) {
                    if (m >= -l && m <= l) {
                        float c = cg_s[(l - LA) * STRIDE + m1 * N2 + m2];
                        ull cc = pk2(c, c);
                        int kk = (l * l - LA * LA) + m + l;
                        acc[kk] = ffma2(cc, pp2, acc[kk]);
                    }
                }
            }
        }
#pragma unroll
        for (int q = 0; q < SK; q++)
            *(ull*)(frag_s + (q * 256 + tid) * 2) = acc[q];   // STS.64 (re,im)
    }
    __syncthreads();  // fragments ready

    // ---- stage 2: weight contraction, 2 k-rows per thread, f32x2 MACs ----
    if (tid < E2) {
        int a = lutA[tid];
        int bd = lutB[tid];
        int kk0 = bd >> 16;
        int dual = (bd >> 15) & 1;
        int ooff = bd & 0x7fff;
        const float4* wp  = (const float4*)(d_wt + a);
        const float4* fp0 = (const float4*)(frag_s + kk0 * 512);
        ull R0 = 0, I0 = 0;
        if (dual) {
            const float4* fp1 = fp0 + 128;
            ull R1 = 0, I1 = 0;
#pragma unroll 4
            for (int p = 0; p < 128; p++) {
                float4 w4 = wp[p * 16];
                ull wxy = pk2(w4.x, w4.y), wyx = pk2(w4.y, w4.x);
                ull wzw = pk2(w4.z, w4.w), wwz = pk2(w4.w, w4.z);
                float4 f0 = fp0[p], f1v = fp1[p];
                ull f0a = pk2(f0.x, f0.y), f0b = pk2(f0.z, f0.w);
                ull f1a = pk2(f1v.x, f1v.y), f1b = pk2(f1v.z, f1v.w);
                R0 = ffma2(wxy, f0a, R0); I0 = ffma2(wyx, f0a, I0);
                R0 = ffma2(wzw, f0b, R0); I0 = ffma2(wwz, f0b, I0);
                R1 = ffma2(wxy, f1a, R1); I1 = ffma2(wyx, f1a, I1);
                R1 = ffma2(wzw, f1b, R1); I1 = ffma2(wwz, f1b, I1);
            }
            float2 r1 = upk(R1), i1 = upk(I1);
            out_s[ooff + 2] += r1.x - r1.y;
            out_s[ooff + 3] += i1.x + i1.y;
        } else {
#pragma unroll 4
            for (int p = 0; p < 128; p++) {
                float4 w4 = wp[p * 16];
                ull wxy = pk2(w4.x, w4.y), wyx = pk2(w4.y, w4.x);
                ull wzw = pk2(w4.z, w4.w), wwz = pk2(w4.w, w4.z);
                float4 f0 = fp0[p];
                ull f0a = pk2(f0.x, f0.y), f0b = pk2(f0.z, f0.w);
                R0 = ffma2(wxy, f0a, R0); I0 = ffma2(wyx, f0a, I0);
                R0 = ffma2(wzw, f0b, R0); I0 = ffma2(wwz, f0b, I0);
            }
        }
        float2 r0 = upk(R0), i0 = upk(I0);
        out_s[ooff]     += r0.x - r0.y;
        out_s[ooff + 1] += i0.x + i0.y;
    }
}

__global__ void __launch_bounds__(256, 2) uf_kernel(Meta meta) {
    extern __shared__ float smem[];
    float* f_s    = smem;                 // 1152 floats
    float* out_s  = smem + 1152;          // 1152
    float* cg_s   = smem + 2304;          // 512
    int*   lutA   = (int*)(smem + 2816);  // 256
    int*   lutB   = lutA + 256;           // 256
    float* frag_s = smem + 3328;          // 10752 (21 rows * 512), 16B-aligned

    int tid = threadIdx.x;
    int b = blockIdx.x;

#pragma unroll
    for (int l = 0; l < 6; l++) {
        int n = 32 * (2 * l + 1);
        const float* src = meta.f[l] + b * n;
        for (int s = tid; s < n; s += 256) f_s[c_FOFF[l] + s] = src[s];
    }
    for (int s = tid; s < 1152; s += 256) out_s[s] = 0.0f;

#define PG(A, B2, G, LA, LB) \
    process_range<A, B2, LA, LB>(G, meta, f_s, out_s, cg_s, lutA, lutB, frag_s, tid)
    PG(0, 0, 0, 0, 0);
    PG(1, 0, 1, 1, 1);
    PG(1, 1, 2, 0, 2);
    PG(2, 0, 3, 2, 2);
    PG(2, 1, 4, 1, 3);
    PG(2, 2, 5, 0, 3);  PG(2, 2, 5, 4, 4);
    PG(3, 0, 6, 3, 3);
    PG(3, 1, 7, 2, 4);
    PG(3, 2, 8, 1, 3);  PG(3, 2, 8, 4, 5);
    PG(3, 3, 9, 0, 3);  PG(3, 3, 9, 4, 5);
    PG(4, 0, 10, 4, 4);
    PG(4, 1, 11, 3, 4); PG(4, 1, 11, 5, 5);
    PG(4, 2, 12, 2, 4); PG(4, 2, 12, 5, 5);
    PG(4, 3, 13, 1, 3); PG(4, 3, 13, 4, 5);
    PG(4, 4, 14, 0, 3); PG(4, 4, 14, 4, 5);
    PG(5, 0, 15, 5, 5);
    PG(5, 1, 16, 4, 5);
    PG(5, 2, 17, 3, 4); PG(5, 2, 17, 5, 5);
    PG(5, 3, 18, 2, 4); PG(5, 3, 18, 5, 5);
    PG(5, 4, 19, 1, 3); PG(5, 4, 19, 4, 5);
    PG(5, 5, 20, 0, 3); PG(5, 5, 20, 4, 5);
#undef PG

    __syncthreads();
    for (int s = tid; s < 1152; s += 256) {
        int l = 0;
#pragma unroll
        for (int ll = 1; ll < 6; ll++)
            if (s >= c_FOFF[ll]) l = ll;
        int rel = s - c_FOFF[l];
        meta.out[c_OUTOFF[l] + b * 32 * (2 * l + 1) + rel] = out_s[s];
    }
}

// ---------------------------------------------------------------------------
// Host launch
// ---------------------------------------------------------------------------
extern "C" void kernel_launch(void* const* d_in, const int* in_sizes, int n_in,
                              void* d_out, int out_size) {
    Meta m;
    const int fsz[6] = {8192, 24576, 40960, 57344, 73728, 90112};
    const int wsz[6] = {49152, 81920, 106496, 114688, 114688, 98304};
    bool used[64];
    for (int i = 0; i < 64; i++) used[i] = false;
    for (int l = 0; l < 6; l++) {
        for (int idx = 0; idx < n_in; idx++) {
            if (!used[idx] && in_sizes[idx] == fsz[l]) {
                m.f[l] = (const float*)d_in[idx];
                used[idx] = true;
                break;
            }
        }
    }
    for (int l = 0; l < 6; l++) {
        for (int idx = 0; idx < n_in; idx++) {
            if (!used[idx] && in_sizes[idx] == wsz[l]) {
                m.w[l] = (const float*)d_in[idx];
                used[idx] = true;
                break;
            }
        }
    }
    m.out = (float*)d_out;

    int off = 0, g = 0, tr = 0;
    int cnt[6] = {0, 0, 0, 0, 0, 0};
    for (int l1 = 0; l1 <= 5; l1++) {
        for (int l2 = 0; l2 <= l1; l2++) {
            int lmin = l1 - l2;
            int lmax = (l1 + l2 < 5) ? (l1 + l2) : 5;
            for (int l = lmin; l <= lmax; l++) {
                m.cg_off[g][l] = off;
                m.trip_l1[tr] = l1;
                m.trip_l2[tr] = l2;
                m.trip_l[tr]  = l;
                m.trip_off[tr] = off;
                tr++;
                off += (2 * l1 + 1) * (2 * l2 + 1);
                m.col_base[g][l] = cnt[l] * 256;
                cnt[l]++;
            }
            g++;
        }
    }

    const int SMEM_BYTES = (3328 + 10752) * 4;  // 56320
    cudaFuncSetAttribute(uf_kernel, cudaFuncAttributeMaxDynamicSharedMemorySize, SMEM_BYTES);

    cg_init_kernel<<<NTRIP, 128>>>(m);
    wt_kernel<<<(565248 + 1023) / 1024, 1024>>>(m);
    uf_kernel<<<256, 256, SMEM_BYTES>>>(m);
}

// round 5
// speedup vs baseline: 1.4303x; 1.4303x over previous
#include <cuda_runtime.h>

#define NG 21
#define NTRIP 69

typedef unsigned long long ull;

struct Meta {
    const float* f[6];
    const float* w[6];
    float*       out;
    int cg_off[NG][6];
    int col_base[NG][6];
    int trip_l1[NTRIP];
    int trip_l2[NTRIP];
    int trip_l[NTRIP];
    int trip_off[NTRIP];
};

__device__ float d_cg[4096];
__device__ float d_wt[565248];   // planar weights: [0,282624) real, [282624,565248) imag

#define WPLANE 282624

__constant__ int c_NUMCOLS[6] = {1536, 2560, 3328, 3584, 3584, 3072};
__constant__ int c_FOFF[7]    = {0, 32, 128, 288, 512, 800, 1152};
__constant__ int c_OUTOFF[6]  = {0, 8192, 32768, 73728, 131072, 204800};
// per-plane l offsets: 16 * cumulative NUMCOLS
__constant__ int c_WTP[7] = {0, 24576, 65536, 118784, 176128, 233472, 282624};

__constant__ double c_fact[17] = {
    1.0, 1.0, 2.0, 6.0, 24.0, 120.0, 720.0, 5040.0, 40320.0, 362880.0,
    3628800.0, 39916800.0, 479001600.0, 6227020800.0, 87178291200.0,
    1307674368000.0, 20922789888000.0
};

// ---- packed f32x2 helpers -------------------------------------------------
__device__ __forceinline__ ull ffma2(ull a, ull b, ull c) {
    ull d; asm("fma.rn.f32x2 %0, %1, %2, %3;" : "=l"(d) : "l"(a), "l"(b), "l"(c)); return d;
}
__device__ __forceinline__ float2 upk(ull a) {
    float2 r; asm("mov.b64 {%0,%1}, %2;" : "=f"(r.x), "=f"(r.y) : "l"(a)); return r;
}

// ---------------------------------------------------------------------------
// CG coefficient init (Racah formula). One CTA per (l1,l2,l) triple.
// ---------------------------------------------------------------------------
__device__ double cg_coeff_d(int l1, int l2, int l, int m1, int m2, int m) {
    double pref = sqrt((2.0 * l + 1.0) * c_fact[l + l1 - l2] * c_fact[l - l1 + l2] *
                       c_fact[l1 + l2 - l] / c_fact[l1 + l2 + l + 1]);
    pref *= sqrt(c_fact[l + m] * c_fact[l - m] * c_fact[l1 - m1] * c_fact[l1 + m1] *
                 c_fact[l2 - m2] * c_fact[l2 + m2]);
    int kmin = 0;
    if (l2 - l - m1 > kmin) kmin = l2 - l - m1;
    if (l1 + m2 - l > kmin) kmin = l1 + m2 - l;
    int kmax = l1 + l2 - l;
    if (l1 - m1 < kmax) kmax = l1 - m1;
    if (l2 + m2 < kmax) kmax = l2 + m2;
    double s = 0.0;
    for (int k = kmin; k <= kmax; k++) {
        double d = c_fact[k] * c_fact[l1 + l2 - l - k] * c_fact[l1 - m1 - k] *
                   c_fact[l2 + m2 - k] * c_fact[l - l2 + m1 + k] * c_fact[l - l1 - m2 + k];
        s += ((k & 1) ? -1.0 : 1.0) / d;
    }
    return pref * s;
}

__global__ void cg_init_kernel(Meta meta) {
    int tr = blockIdx.x;
    int l1 = meta.trip_l1[tr], l2 = meta.trip_l2[tr], l = meta.trip_l[tr];
    int off = meta.trip_off[tr];
    int n1 = 2 * l1 + 1, n2 = 2 * l2 + 1;
    int idx = threadIdx.x;
    if (idx >= n1 * n2) return;
    int m1i = idx / n2, m2i = idx % n2;
    int m1 = m1i - l1, m2 = m2i - l2, m = m1 + m2;
    float c = 0.0f;
    if (m >= -l && m <= l)
        c = (float)cg_coeff_d(l1, l2, l, m1, m2, m);
    d_cg[off + idx] = c;
}

// ---------------------------------------------------------------------------
// Weight transpose to planar layout:
//   plane p (0=real, 1=imag), per l: wt[c/4][t][4] -> element (l, t, c, p)
// ---------------------------------------------------------------------------
__global__ void wt_kernel(Meta m) {
    int j = blockIdx.x * blockDim.x + threadIdx.x;
    if (j >= 565248) return;
    int plane = (j >= WPLANE) ? 1 : 0;
    int r0 = j - plane * WPLANE;
    int l = 0;
#pragma unroll
    for (int ll = 1; ll < 6; ll++)
        if (r0 >= c_WTP[ll]) l = ll;
    int r = r0 - c_WTP[l];
    int j3 = r & 3;
    int t = (r >> 2) & 15;
    int c4 = r >> 6;
    int c = c4 * 4 + j3;
    d_wt[j] = m.w[l][(t * c_NUMCOLS[l] + c) * 2 + plane];
}

// ---------------------------------------------------------------------------
// Main fused kernel
// ---------------------------------------------------------------------------
template <int L1, int L2, int LA, int LB>
__device__ __forceinline__ void process_range(
    int g, const Meta& meta, float* __restrict__ f_s, float* __restrict__ out_s,
    float* __restrict__ cg_s, int* __restrict__ lutA, int* __restrict__ lutB,
    float* __restrict__ frag_r, float* __restrict__ frag_i, int tid)
{
    constexpr int N1 = 2 * L1 + 1;
    constexpr int N2 = 2 * L2 + 1;
    constexpr int STRIDE = N1 * N2;
    constexpr int NL = LB - LA + 1;
    constexpr int SK = (LB + 1) * (LB + 1) - LA * LA;  // sum of (2l+1)
    constexpr int E = 16 * SK;

    __syncthreads();  // prior phase done with cg/lut/frag

    {
        const float* src = d_cg + meta.cg_off[g][LA];
        for (int s = tid; s < NL * STRIDE; s += 256) cg_s[s] = src[s];
    }
    // build (l,t,k) work list
    for (int e = tid; e < E; e += 256) {
        int t = e & 15, kk = e >> 4;
        int l = LA;
#pragma unroll
        for (int ll = LA; ll < LB; ll++)
            if (kk >= (ll + 1) * (ll + 1) - LA * LA) l = ll + 1;
        int k = kk - (l * l - LA * LA);
        lutA[e] = c_WTP[l] + (meta.col_base[g][l] >> 2) * 64 + t * 4;
        lutB[e] = (kk << 16) | (c_FOFF[l] + (t * (2 * l + 1) + k) * 2);
    }
    __syncthreads();  // cg + lut ready

    // ---- stage 1: CG fragments, thread = (i,j) channel pair = column ----
    {
        int i = tid >> 4, j = tid & 15;
        float accr[SK], acci[SK];
#pragma unroll
        for (int q = 0; q < SK; q++) { accr[q] = 0.0f; acci[q] = 0.0f; }
        const float* f1 = f_s + c_FOFF[L1] + i * N1 * 2;
        const float* f2 = f_s + c_FOFF[L2] + j * N2 * 2;
#pragma unroll
        for (int m1 = 0; m1 < N1; m1++) {
            float ar = f1[2 * m1], ai = f1[2 * m1 + 1];
#pragma unroll
            for (int m2 = 0; m2 < N2; m2++) {
                float br = f2[2 * m2], bi = f2[2 * m2 + 1];
                float pr = ar * br - ai * bi;
                float pi = ar * bi + ai * br;
                int m = m1 + m2 - L1 - L2;
#pragma unroll
                for (int l = LA; l <= LB; l++) {
                    if (m >= -l && m <= l) {
                        float c = cg_s[(l - LA) * STRIDE + m1 * N2 + m2];
                        int kk = (l * l - LA * LA) + m + l;
                        accr[kk] += c * pr;
                        acci[kk] += c * pi;
                    }
                }
            }
        }
#pragma unroll
        for (int q = 0; q < SK; q++) {
            frag_r[q * 256 + tid] = accr[q];
            frag_i[q * 256 + tid] = acci[q];
        }
    }
    __syncthreads();  // fragments ready

    // ---- stage 2: planar weight contraction, channel-packed f32x2 MACs ----
    for (int e = tid; e < E; e += 256) {
        int a = lutA[e];
        int bd = lutB[e];
        int kk = bd >> 16;
        int ooff = bd & 0xffff;
        const ulonglong2* wr = (const ulonglong2*)(d_wt + a);
        const ulonglong2* wi = (const ulonglong2*)(d_wt + WPLANE + a);
        const ulonglong2* fr = (const ulonglong2*)(frag_r + kk * 256);
        const ulonglong2* fi = (const ulonglong2*)(frag_i + kk * 256);
        ull A = 0, B = 0, C = 0, D = 0;
#pragma unroll 4
        for (int p = 0; p < 64; p++) {
            ulonglong2 w_r = wr[p * 16];   // stride 64 floats = 16 ull2
            ulonglong2 w_i = wi[p * 16];
            ulonglong2 f_r = fr[p];
            ulonglong2 f_i = fi[p];
            A = ffma2(w_r.x, f_r.x, A);
            B = ffma2(w_i.x, f_i.x, B);
            C = ffma2(w_r.x, f_i.x, C);
            D = ffma2(w_i.x, f_r.x, D);
            A = ffma2(w_r.y, f_r.y, A);
            B = ffma2(w_i.y, f_i.y, B);
            C = ffma2(w_r.y, f_i.y, C);
            D = ffma2(w_i.y, f_r.y, D);
        }
        float2 a2 = upk(A), b2 = upk(B), c2 = upk(C), d2 = upk(D);
        out_s[ooff]     += (a2.x + a2.y) - (b2.x + b2.y);
        out_s[ooff + 1] += (c2.x + c2.y) + (d2.x + d2.y);
    }
}

__global__ void __launch_bounds__(256, 2) uf_kernel(Meta meta) {
    extern __shared__ float smem[];
    float* f_s    = smem;                 // 1152 floats
    float* out_s  = smem + 1152;          // 1152
    float* cg_s   = smem + 2304;          // 512
    int*   lutA   = (int*)(smem + 2816);  // 352
    int*   lutB   = lutA + 352;           // 352
    float* frag_r = smem + 3520;          // 5376 (21 rows * 256)
    float* frag_i = smem + 8896;          // 5376

    int tid = threadIdx.x;
    int b = blockIdx.x;

#pragma unroll
    for (int l = 0; l < 6; l++) {
        int n = 32 * (2 * l + 1);
        const float* src = meta.f[l] + b * n;
        for (int s = tid; s < n; s += 256) f_s[c_FOFF[l] + s] = src[s];
    }
    for (int s = tid; s < 1152; s += 256) out_s[s] = 0.0f;

#define PG(A, B2, G, LA, LB) \
    process_range<A, B2, LA, LB>(G, meta, f_s, out_s, cg_s, lutA, lutB, frag_r, frag_i, tid)
    PG(0, 0, 0, 0, 0);
    PG(1, 0, 1, 1, 1);
    PG(1, 1, 2, 0, 2);
    PG(2, 0, 3, 2, 2);
    PG(2, 1, 4, 1, 3);
    PG(2, 2, 5, 0, 3);  PG(2, 2, 5, 4, 4);
    PG(3, 0, 6, 3, 3);
    PG(3, 1, 7, 2, 4);
    PG(3, 2, 8, 1, 3);  PG(3, 2, 8, 4, 5);
    PG(3, 3, 9, 0, 3);  PG(3, 3, 9, 4, 5);
    PG(4, 0, 10, 4, 4);
    PG(4, 1, 11, 3, 4); PG(4, 1, 11, 5, 5);
    PG(4, 2, 12, 2, 4); PG(4, 2, 12, 5, 5);
    PG(4, 3, 13, 1, 3); PG(4, 3, 13, 4, 5);
    PG(4, 4, 14, 0, 3); PG(4, 4, 14, 4, 5);
    PG(5, 0, 15, 5, 5);
    PG(5, 1, 16, 4, 5);
    PG(5, 2, 17, 3, 4); PG(5, 2, 17, 5, 5);
    PG(5, 3, 18, 2, 4); PG(5, 3, 18, 5, 5);
    PG(5, 4, 19, 1, 3); PG(5, 4, 19, 4, 5);
    PG(5, 5, 20, 0, 3); PG(5, 5, 20, 4, 5);
#undef PG

    __syncthreads();
    for (int s = tid; s < 1152; s += 256) {
        int l = 0;
#pragma unroll
        for (int ll = 1; ll < 6; ll++)
            if (s >= c_FOFF[ll]) l = ll;
        int rel = s - c_FOFF[l];
        meta.out[c_OUTOFF[l] + b * 32 * (2 * l + 1) + rel] = out_s[s];
    }
}

// ---------------------------------------------------------------------------
// Host launch
// ---------------------------------------------------------------------------
extern "C" void kernel_launch(void* const* d_in, const int* in_sizes, int n_in,
                              void* d_out, int out_size) {
    Meta m;
    const int fsz[6] = {8192, 24576, 40960, 57344, 73728, 90112};
    const int wsz[6] = {49152, 81920, 106496, 114688, 114688, 98304};
    bool used[64];
    for (int i = 0; i < 64; i++) used[i] = false;
    for (int l = 0; l < 6; l++) {
        for (int idx = 0; idx < n_in; idx++) {
            if (!used[idx] && in_sizes[idx] == fsz[l]) {
                m.f[l] = (const float*)d_in[idx];
                used[idx] = true;
                break;
            }
        }
    }
    for (int l = 0; l < 6; l++) {
        for (int idx = 0; idx < n_in; idx++) {
            if (!used[idx] && in_sizes[idx] == wsz[l]) {
                m.w[l] = (const float*)d_in[idx];
                used[idx] = true;
                break;
            }
        }
    }
    m.out = (float*)d_out;

    int off = 0, g = 0, tr = 0;
    int cnt[6] = {0, 0, 0, 0, 0, 0};
    for (int l1 = 0; l1 <= 5; l1++) {
        for (int l2 = 0; l2 <= l1; l2++) {
            int lmin = l1 - l2;
            int lmax = (l1 + l2 < 5) ? (l1 + l2) : 5;
            for (int l = lmin; l <= lmax; l++) {
                m.cg_off[g][l] = off;
                m.trip_l1[tr] = l1;
                m.trip_l2[tr] = l2;
                m.trip_l[tr]  = l;
                m.trip_off[tr] = off;
                tr++;
                off += (2 * l1 + 1) * (2 * l2 + 1);
                m.col_base[g][l] = cnt[l] * 256;
                cnt[l]++;
            }
            g++;
        }
    }

    const int SMEM_BYTES = (3520 + 10752) * 4;  // 57088
    cudaFuncSetAttribute(uf_kernel, cudaFuncAttributeMaxDynamicSharedMemorySize, SMEM_BYTES);

    cg_init_kernel<<<NTRIP, 128>>>(m);
    wt_kernel<<<(565248 + 1023) / 1024, 1024>>>(m);
    uf_kernel<<<256, 256, SMEM_BYTES>>>(m);
}

// round 6
// speedup vs baseline: 1.6840x; 1.1774x over previous
#include <cuda_runtime.h>

#define NG 21
#define NTRIP 69

typedef unsigned long long ull;

struct Meta {
    const float* f[6];
    const float* w[6];
    float*       out;
    int cg_off[NG][6];
    int col_base[NG][6];
    int trip_l1[NTRIP];
    int trip_l2[NTRIP];
    int trip_l[NTRIP];
    int trip_off[NTRIP];
};

__device__ float d_cg[4096];
__device__ float d_wt[565248];   // planar weights: [0,282624) real, [282624,565248) imag

#define WPLANE 282624

__constant__ int c_NUMCOLS[6] = {1536, 2560, 3328, 3584, 3584, 3072};
__constant__ int c_FOFF[7]    = {0, 32, 128, 288, 512, 800, 1152};
__constant__ int c_OUTOFF[6]  = {0, 8192, 32768, 73728, 131072, 204800};
__constant__ int c_WTP[7] = {0, 24576, 65536, 118784, 176128, 233472, 282624};

__constant__ double c_fact[17] = {
    1.0, 1.0, 2.0, 6.0, 24.0, 120.0, 720.0, 5040.0, 40320.0, 362880.0,
    3628800.0, 39916800.0, 479001600.0, 6227020800.0, 87178291200.0,
    1307674368000.0, 20922789888000.0
};

// ---- packed f32x2 helpers -------------------------------------------------
__device__ __forceinline__ ull ffma2(ull a, ull b, ull c) {
    ull d; asm("fma.rn.f32x2 %0, %1, %2, %3;" : "=l"(d) : "l"(a), "l"(b), "l"(c)); return d;
}
__device__ __forceinline__ float2 upk(ull a) {
    float2 r; asm("mov.b64 {%0,%1}, %2;" : "=f"(r.x), "=f"(r.y) : "l"(a)); return r;
}

// ---------------------------------------------------------------------------
// CG coefficient init (Racah formula). One CTA per (l1,l2,l) triple.
// ---------------------------------------------------------------------------
__device__ double cg_coeff_d(int l1, int l2, int l, int m1, int m2, int m) {
    double pref = sqrt((2.0 * l + 1.0) * c_fact[l + l1 - l2] * c_fact[l - l1 + l2] *
                       c_fact[l1 + l2 - l] / c_fact[l1 + l2 + l + 1]);
    pref *= sqrt(c_fact[l + m] * c_fact[l - m] * c_fact[l1 - m1] * c_fact[l1 + m1] *
                 c_fact[l2 - m2] * c_fact[l2 + m2]);
    int kmin = 0;
    if (l2 - l - m1 > kmin) kmin = l2 - l - m1;
    if (l1 + m2 - l > kmin) kmin = l1 + m2 - l;
    int kmax = l1 + l2 - l;
    if (l1 - m1 < kmax) kmax = l1 - m1;
    if (l2 + m2 < kmax) kmax = l2 + m2;
    double s = 0.0;
    for (int k = kmin; k <= kmax; k++) {
        double d = c_fact[k] * c_fact[l1 + l2 - l - k] * c_fact[l1 - m1 - k] *
                   c_fact[l2 + m2 - k] * c_fact[l - l2 + m1 + k] * c_fact[l - l1 - m2 + k];
        s += ((k & 1) ? -1.0 : 1.0) / d;
    }
    return pref * s;
}

__global__ void cg_init_kernel(Meta meta) {
    int tr = blockIdx.x;
    int l1 = meta.trip_l1[tr], l2 = meta.trip_l2[tr], l = meta.trip_l[tr];
    int off = meta.trip_off[tr];
    int n1 = 2 * l1 + 1, n2 = 2 * l2 + 1;
    int idx = threadIdx.x;
    if (idx >= n1 * n2) return;
    int m1i = idx / n2, m2i = idx % n2;
    int m1 = m1i - l1, m2 = m2i - l2, m = m1 + m2;
    float c = 0.0f;
    if (m >= -l && m <= l)
        c = (float)cg_coeff_d(l1, l2, l, m1, m2, m);
    d_cg[off + idx] = c;
}

// ---------------------------------------------------------------------------
// Weight transpose to planar layout:
//   plane p (0=real, 1=imag), per l: wt[c/4][t][4] -> element (l, t, c, p)
// ---------------------------------------------------------------------------
__global__ void wt_kernel(Meta m) {
    int j = blockIdx.x * blockDim.x + threadIdx.x;
    if (j >= 565248) return;
    int plane = (j >= WPLANE) ? 1 : 0;
    int r0 = j - plane * WPLANE;
    int l = 0;
#pragma unroll
    for (int ll = 1; ll < 6; ll++)
        if (r0 >= c_WTP[ll]) l = ll;
    int r = r0 - c_WTP[l];
    int j3 = r & 3;
    int t = (r >> 2) & 15;
    int c4 = r >> 6;
    int c = c4 * 4 + j3;
    d_wt[j] = m.w[l][(t * c_NUMCOLS[l] + c) * 2 + plane];
}

// ---------------------------------------------------------------------------
// Stage-2 helpers (single copies, shared by all 31 subrange instantiations)
// ---------------------------------------------------------------------------
template <int CNT>
__device__ __forceinline__ void s2_acc(const ulonglong2* __restrict__ wr,
                                       const ulonglong2* __restrict__ wi,
                                       const ulonglong2* __restrict__ fr,
                                       const ulonglong2* __restrict__ fi,
                                       int len, int ooff, float* out_s)
{
    ull A[CNT], Bq[CNT], C[CNT], D[CNT];
#pragma unroll
    for (int q = 0; q < CNT; q++) { A[q] = 0; Bq[q] = 0; C[q] = 0; D[q] = 0; }
#pragma unroll 2
    for (int p = 0; p < len; p++) {
        ulonglong2 w_r = wr[p * 16];
        ulonglong2 w_i = wi[p * 16];
#pragma unroll
        for (int q = 0; q < CNT; q++) {
            ulonglong2 f_r = fr[q * 64 + p];
            ulonglong2 f_i = fi[q * 64 + p];
            A[q]  = ffma2(w_r.x, f_r.x, A[q]);
            A[q]  = ffma2(w_r.y, f_r.y, A[q]);
            Bq[q] = ffma2(w_i.x, f_i.x, Bq[q]);
            Bq[q] = ffma2(w_i.y, f_i.y, Bq[q]);
            C[q]  = ffma2(w_r.x, f_i.x, C[q]);
            C[q]  = ffma2(w_r.y, f_i.y, C[q]);
            D[q]  = ffma2(w_i.x, f_r.x, D[q]);
            D[q]  = ffma2(w_i.y, f_r.y, D[q]);
        }
    }
#pragma unroll
    for (int q = 0; q < CNT; q++) {
        float2 a2 = upk(A[q]), b2 = upk(Bq[q]), c2 = upk(C[q]), d2 = upk(D[q]);
        atomicAdd(&out_s[ooff + 2 * q],     (a2.x + a2.y) - (b2.x + b2.y));
        atomicAdd(&out_s[ooff + 2 * q + 1], (c2.x + c2.y) + (d2.x + d2.y));
    }
}

__device__ __noinline__ void stage2(int E, const int* lutA, const int* lutB,
                                    const float* frag_r, const float* frag_i,
                                    float* out_s, int tid)
{
    for (int e = tid; e < E; e += 256) {
        int a = lutA[e], bd = lutB[e];
        int woff   = a & 0x7FFFF;
        int pstart = (a >> 19) & 63;
        int len    = (a >> 25) & 127;
        int kk0 = bd >> 16;
        int cnt = (bd >> 13) & 7;
        int ooff = bd & 0x1FFF;
        const ulonglong2* wr = (const ulonglong2*)(d_wt + woff);
        const ulonglong2* wi = (const ulonglong2*)(d_wt + WPLANE + woff);
        const ulonglong2* fr = (const ulonglong2*)frag_r + kk0 * 64 + pstart;
        const ulonglong2* fi = (const ulonglong2*)frag_i + kk0 * 64 + pstart;
        if (cnt == 4)      s2_acc<4>(wr, wi, fr, fi, len, ooff, out_s);
        else if (cnt == 3) s2_acc<3>(wr, wi, fr, fi, len, ooff, out_s);
        else               s2_acc<1>(wr, wi, fr, fi, len, ooff, out_s);
    }
}

// Build the (l, t, k-quad, c-chunk) work list for one subrange.
__device__ __noinline__ void build_lut(int LA, int LB, int lcs, int E,
                                       const int* colbase6,
                                       int* lutA, int* lutB, int tid)
{
    int csplit = 1 << lcs;
    int len = 64 >> lcs;
    for (int e = tid; e < E; e += 256) {
        int t = e & 15;
        int r = e >> 4;
        int ch = r & (csplit - 1);
        int blk = r >> lcs;
        int l = LA, cum = 0;
        for (int ll = LA; ll <= LB; ll++) {
            int nq = (ll + 2) >> 1;            // ceil((2l+1)/4)
            if (blk < cum + nq) { l = ll; break; }
            cum += nq;
        }
        int k0 = (blk - cum) * 4;
        int tl = 2 * l + 1;
        int cnt = tl - k0; if (cnt > 4) cnt = 4;
        int pstart = ch * len;
        int woff = c_WTP[l] + ((colbase6[l] >> 2) + pstart) * 64 + t * 4;
        int kk0 = (l * l - LA * LA) + k0;
        int ooff = c_FOFF[l] + (t * tl + k0) * 2;
        lutA[e] = woff | (pstart << 19) | (len << 25);
        lutB[e] = (kk0 << 16) | (cnt << 13) | ooff;
    }
}

// ---------------------------------------------------------------------------
// Main fused kernel
// ---------------------------------------------------------------------------
template <int L1, int L2, int LA, int LB>
__device__ __forceinline__ void process_range(
    int g, const Meta& meta, float* __restrict__ f_s, float* __restrict__ out_s,
    float* __restrict__ cg_s, int* __restrict__ lutA, int* __restrict__ lutB,
    float* __restrict__ frag_r, float* __restrict__ frag_i, int tid)
{
    constexpr int N1 = 2 * L1 + 1;
    constexpr int N2 = 2 * L2 + 1;
    constexpr int STRIDE = N1 * N2;
    constexpr int NL = LB - LA + 1;
    constexpr int SK = (LB + 1) * (LB + 1) - LA * LA;  // sum of (2l+1)
    // number of k-quads across the l range: nq(l) = (l+2)/2
    constexpr int KQ =
        (((LA + 0) <= LB) ? ((LA + 0 + 2) / 2) : 0) +
        (((LA + 1) <= LB) ? ((LA + 1 + 2) / 2) : 0) +
        (((LA + 2) <= LB) ? ((LA + 2 + 2) / 2) : 0) +
        (((LA + 3) <= LB) ? ((LA + 3 + 2) / 2) : 0) +
        (((LA + 4) <= LB) ? ((LA + 4 + 2) / 2) : 0) +
        (((LA + 5) <= LB) ? ((LA + 5 + 2) / 2) : 0);
    constexpr int E0 = 16 * KQ;
    constexpr int LCS = (E0 >= 256) ? 0 : ((E0 >= 128) ? 1 : ((E0 >= 64) ? 2 : ((E0 >= 32) ? 3 : 4)));
    constexpr int E = E0 << LCS;

    __syncthreads();  // prior phase done with cg/lut/frag

    {
        const float* src = d_cg + meta.cg_off[g][LA];
        for (int s = tid; s < NL * STRIDE; s += 256) cg_s[s] = src[s];
    }
    build_lut(LA, LB, LCS, E, meta.col_base[g], lutA, lutB, tid);
    __syncthreads();  // cg + lut ready

    // ---- stage 1: CG fragments, thread = (i,j) channel pair = column ----
    {
        int i = tid >> 4, j = tid & 15;
        float accr[SK], acci[SK];
#pragma unroll
        for (int q = 0; q < SK; q++) { accr[q] = 0.0f; acci[q] = 0.0f; }
        const float* f1 = f_s + c_FOFF[L1] + i * N1 * 2;
        const float* f2 = f_s + c_FOFF[L2] + j * N2 * 2;
#pragma unroll
        for (int m1 = 0; m1 < N1; m1++) {
            float ar = f1[2 * m1], ai = f1[2 * m1 + 1];
#pragma unroll
            for (int m2 = 0; m2 < N2; m2++) {
                float br = f2[2 * m2], bi = f2[2 * m2 + 1];
                float pr = ar * br - ai * bi;
                float pi = ar * bi + ai * br;
                int m = m1 + m2 - L1 - L2;
#pragma unroll
                for (int l = LA; l <= LB; l++) {
                    if (m >= -l && m <= l) {
                        float c = cg_s[(l - LA) * STRIDE + m1 * N2 + m2];
                        int kk = (l * l - LA * LA) + m + l;
                        accr[kk] += c * pr;
                        acci[kk] += c * pi;
                    }
                }
            }
        }
#pragma unroll
        for (int q = 0; q < SK; q++) {
            frag_r[q * 256 + tid] = accr[q];
            frag_i[q * 256 + tid] = acci[q];
        }
    }
    __syncthreads();  // fragments ready

    stage2(E, lutA, lutB, frag_r, frag_i, out_s, tid);
}

__global__ void __launch_bounds__(256, 2) uf_kernel(Meta meta) {
    extern __shared__ float smem[];
    float* f_s    = smem;                 // 1152 floats
    float* out_s  = smem + 1152;          // 1152
    float* cg_s   = smem + 2304;          // 512
    int*   lutA   = (int*)(smem + 2816);  // 448
    int*   lutB   = lutA + 448;           // 448
    float* frag_r = smem + 3712;          // 5376 (21 rows * 256), 16B-aligned
    float* frag_i = smem + 9088;          // 5376

    int tid = threadIdx.x;
    int b = blockIdx.x;

#pragma unroll
    for (int l = 0; l < 6; l++) {
        int n = 32 * (2 * l + 1);
        const float* src = meta.f[l] + b * n;
        for (int s = tid; s < n; s += 256) f_s[c_FOFF[l] + s] = src[s];
    }
    for (int s = tid; s < 1152; s += 256) out_s[s] = 0.0f;

#define PG(A, B2, G, LA, LB) \
    process_range<A, B2, LA, LB>(G, meta, f_s, out_s, cg_s, lutA, lutB, frag_r, frag_i, tid)
    PG(0, 0, 0, 0, 0);
    PG(1, 0, 1, 1, 1);
    PG(1, 1, 2, 0, 2);
    PG(2, 0, 3, 2, 2);
    PG(2, 1, 4, 1, 3);
    PG(2, 2, 5, 0, 3);  PG(2, 2, 5, 4, 4);
    PG(3, 0, 6, 3, 3);
    PG(3, 1, 7, 2, 4);
    PG(3, 2, 8, 1, 3);  PG(3, 2, 8, 4, 5);
    PG(3, 3, 9, 0, 3);  PG(3, 3, 9, 4, 5);
    PG(4, 0, 10, 4, 4);
    PG(4, 1, 11, 3, 4); PG(4, 1, 11, 5, 5);
    PG(4, 2, 12, 2, 4); PG(4, 2, 12, 5, 5);
    PG(4, 3, 13, 1, 3); PG(4, 3, 13, 4, 5);
    PG(4, 4, 14, 0, 3); PG(4, 4, 14, 4, 5);
    PG(5, 0, 15, 5, 5);
    PG(5, 1, 16, 4, 5);
    PG(5, 2, 17, 3, 4); PG(5, 2, 17, 5, 5);
    PG(5, 3, 18, 2, 4); PG(5, 3, 18, 5, 5);
    PG(5, 4, 19, 1, 3); PG(5, 4, 19, 4, 5);
    PG(5, 5, 20, 0, 3); PG(5, 5, 20, 4, 5);
#undef PG

    __syncthreads();
    for (int s = tid; s < 1152; s += 256) {
        int l = 0;
#pragma unroll
        for (int ll = 1; ll < 6; ll++)
            if (s >= c_FOFF[ll]) l = ll;
        int rel = s - c_FOFF[l];
        meta.out[c_OUTOFF[l] + b * 32 * (2 * l + 1) + rel] = out_s[s];
    }
}

// ---------------------------------------------------------------------------
// Host launch
// ---------------------------------------------------------------------------
extern "C" void kernel_launch(void* const* d_in, const int* in_sizes, int n_in,
                              void* d_out, int out_size) {
    Meta m;
    const int fsz[6] = {8192, 24576, 40960, 57344, 73728, 90112};
    const int wsz[6] = {49152, 81920, 106496, 114688, 114688, 98304};
    bool used[64];
    for (int i = 0; i < 64; i++) used[i] = false;
    for (int l = 0; l < 6; l++) {
        for (int idx = 0; idx < n_in; idx++) {
            if (!used[idx] && in_sizes[idx] == fsz[l]) {
                m.f[l] = (const float*)d_in[idx];
                used[idx] = true;
                break;
            }
        }
    }
    for (int l = 0; l < 6; l++) {
        for (int idx = 0; idx < n_in; idx++) {
            if (!used[idx] && in_sizes[idx] == wsz[l]) {
                m.w[l] = (const float*)d_in[idx];
                used[idx] = true;
                break;
            }
        }
    }
    m.out = (float*)d_out;

    int off = 0, g = 0, tr = 0;
    int cnt[6] = {0, 0, 0, 0, 0, 0};
    for (int l1 = 0; l1 <= 5; l1++) {
        for (int l2 = 0; l2 <= l1; l2++) {
            int lmin = l1 - l2;
            int lmax = (l1 + l2 < 5) ? (l1 + l2) : 5;
            for (int l = lmin; l <= lmax; l++) {
                m.cg_off[g][l] = off;
                m.trip_l1[tr] = l1;
                m.trip_l2[tr] = l2;
                m.trip_l[tr]  = l;
                m.trip_off[tr] = off;
                tr++;
                off += (2 * l1 + 1) * (2 * l2 + 1);
                m.col_base[g][l] = cnt[l] * 256;
                cnt[l]++;
            }
            g++;
        }
    }

    const int SMEM_BYTES = (3712 + 10752) * 4;  // 57856
    cudaFuncSetAttribute(uf_kernel, cudaFuncAttributeMaxDynamicSharedMemorySize, SMEM_BYTES);

    cg_init_kernel<<<NTRIP, 128>>>(m);
    wt_kernel<<<(565248 + 1023) / 1024, 1024>>>(m);
    uf_kernel<<<256, 256, SMEM_BYTES>>>(m);
}